// round 13
// baseline (speedup 1.0000x reference)
#include <cuda_runtime.h>
#include <math.h>

#define N_NODES 50000
#define D 100
#define DP 104                 // padded row: 100 premultiplied feats + w + 3 pad
#define E_EDGES 800000
#define OUTD 300

// Scratch (allocation-free). g_gw[b][node*DP..] = [w*f[0..99], w, 0,0,0].
// w[c] = exp(score[c]); score in [-1,1] so exp never overflows and the
// reference's max-subtraction cancels exactly in the softmax ratio.
__device__ __align__(16) float g_gw[2][(size_t)N_NODES * DP + 32];
__device__ __align__(16) float g_nr[128];
__device__ __align__(16) int g_coff[E_EDGES + 32];
__device__ int g_rowptr[N_NODES + 1];

typedef unsigned long long u64;

// ---------------------------------------------------------------------------
__device__ __forceinline__ void fadd2(u64& a, u64 b) {
    asm("add.rn.f32x2 %0, %0, %1;" : "+l"(a) : "l"(b));
}
__device__ __forceinline__ float2 unpack2(u64 v) {
    float2 r;
    asm("mov.b64 {%0, %1}, %2;" : "=f"(r.x), "=f"(r.y) : "l"(v));
    return r;
}
__device__ __forceinline__ float tanha(float x) {      // HW tanh approx
    float r;
    asm("tanh.approx.f32 %0, %1;" : "=f"(r) : "f"(x));
    return r;
}

// ---------------------------------------------------------------------------
// Prep: packed col offsets + CSR row pointers (rows sorted; binary search).
// Block 0 threads 0..127 additionally build the normalized none_relation.
__global__ void prep_kernel(const int* __restrict__ adj,
                            const float* __restrict__ none_rel) {
    if (blockIdx.x == 0 && threadIdx.x < 128) {
        __shared__ float ssum[128];
        int t = threadIdx.x;
        float v = (t < D) ? none_rel[t] : 0.f;
        ssum[t] = v * v;
        __syncthreads();
        for (int s = 64; s > 0; s >>= 1) {
            if (t < s) ssum[t] += ssum[t + s];
            __syncthreads();
        }
        float inv = 1.f / fmaxf(sqrtf(ssum[0]), 1e-12f);
        g_nr[t] = (t < D) ? v * inv : 0.f;
    }
    int i = blockIdx.x * blockDim.x + threadIdx.x;
    if (i < E_EDGES)
        g_coff[i] = adj[2 * i + 1] * DP;
    if (i <= N_NODES) {
        int lo = 0, hi = E_EDGES;
        while (lo < hi) {
            int mid = (lo + hi) >> 1;
            if (adj[2 * mid] < i) lo = mid + 1; else hi = mid;
        }
        g_rowptr[i] = lo;
    }
}

// ---------------------------------------------------------------------------
// Warp-collective epilogue: from this node's fp32 feature chunk r (lanes 0..24),
// compute w = exp(-dot(l2norm(r), nr)); store [w*r, w, 0,0,0] into g_gw[fbuf].
__device__ __forceinline__ void epilogue_store(float4 r, int lane, int node, int fbuf) {
    float dot = 0.f, ss = 0.f;
    if (lane < 25) {
        float4 nv = *(const float4*)(g_nr + lane * 4);
        dot = r.x * nv.x + r.y * nv.y + r.z * nv.z + r.w * nv.w;
        ss  = r.x * r.x + r.y * r.y + r.z * r.z + r.w * r.w;
    }
    #pragma unroll
    for (int o = 16; o; o >>= 1) {
        dot += __shfl_xor_sync(0xffffffffu, dot, o);
        ss  += __shfl_xor_sync(0xffffffffu, ss, o);
    }
    float w = __expf(-dot / fmaxf(sqrtf(ss), 1e-12f));
    if (lane < 26) {
        float4 s = (lane < 25)
            ? make_float4(w * r.x, w * r.y, w * r.z, w * r.w)
            : make_float4(w, 0.f, 0.f, 0.f);
        *(float4*)(g_gw[fbuf] + (size_t)node * DP + lane * 4) = s;
    }
}

// ---------------------------------------------------------------------------
// Layer 0: r = tanh(features); write out cols [0,D), build g_gw[0].
__global__ void tanh_score_kernel(const float* __restrict__ feat,
                                  float* __restrict__ out) {
    int node = (blockIdx.x * blockDim.x + threadIdx.x) >> 5;
    int lane = threadIdx.x & 31;
    if (node >= N_NODES) return;
    float4 r = make_float4(0.f, 0.f, 0.f, 0.f);
    if (lane < 25) {
        float4 v = *(const float4*)(feat + (size_t)node * D + lane * 4);
        r.x = tanha(v.x); r.y = tanha(v.y); r.z = tanha(v.z); r.w = tanha(v.w);
        *(float4*)(out + (size_t)node * OUTD + lane * 4) = r;
    }
    epilogue_store(r, lane, node, 0);
}

// ---------------------------------------------------------------------------
// Pipeline helpers (inline functions instead of token-pasting macros).
__device__ __forceinline__ void gather4(bool act, const float* __restrict__ gwb,
                                        int4 q, int laneoff,
                                        ulonglong2& v0, ulonglong2& v1,
                                        ulonglong2& v2, ulonglong2& v3) {
    if (act) {
        v0 = *(const ulonglong2*)(gwb + q.x + laneoff);
        v1 = *(const ulonglong2*)(gwb + q.y + laneoff);
        v2 = *(const ulonglong2*)(gwb + q.z + laneoff);
        v3 = *(const ulonglong2*)(gwb + q.w + laneoff);
    }
}
__device__ __forceinline__ void consume4(bool act,
                                         u64& a0, u64& a1, u64& a2, u64& a3,
                                         const ulonglong2& v0, const ulonglong2& v1,
                                         const ulonglong2& v2, const ulonglong2& v3) {
    if (act) {
        fadd2(a0, v0.x); fadd2(a1, v0.y);
        fadd2(a2, v1.x); fadd2(a3, v1.y);
        fadd2(a0, v2.x); fadd2(a1, v2.y);
        fadd2(a2, v3.x); fadd2(a3, v3.y);
    }
}

// ---------------------------------------------------------------------------
// Attention row kernel: gather-sum of fp32 premultiplied rows with a forced
// modulo-scheduled 2-batch pipeline (both batches live across iterations).
// Lanes 0..24 accumulate features; lane 25's first slot accumulates den.
template <bool LAST>
__global__ void __launch_bounds__(128) row_kernel(int buf, float* __restrict__ out,
                                                  int outoff) {
    int row = (blockIdx.x * blockDim.x + threadIdx.x) >> 5;
    int lane = threadIdx.x & 31;
    if (row >= N_NODES) return;
    int beg = g_rowptr[row];
    int end = g_rowptr[row + 1];
    const float* __restrict__ gwb = g_gw[buf];
    bool act = (lane < 26);
    int laneoff = lane * 4;

    u64 a0 = 0ull, a1 = 0ull, a2 = 0ull, a3 = 0ull;

    int e = beg;
    // Peel to int4-aligned coff reads.
    int pre = (4 - (beg & 3)) & 3;
    if (pre > end - beg) pre = end - beg;
    for (int k = 0; k < pre; ++k, ++e) {
        if (act) {
            ulonglong2 v = *(const ulonglong2*)(gwb + g_coff[e] + laneoff);
            fadd2(a0, v.x); fadd2(a1, v.y);
        }
    }

    if (e + 8 <= end) {
        ulonglong2 A0, A1, A2, A3, B0, B1, B2, B3;
        int4 qa = *(const int4*)(g_coff + e);
        int4 qb = *(const int4*)(g_coff + e + 4);
        gather4(act, gwb, qa, laneoff, A0, A1, A2, A3);
        gather4(act, gwb, qb, laneoff, B0, B1, B2, B3);
        e += 8;
        for (; e + 8 <= end; e += 8) {
            int4 q0 = *(const int4*)(g_coff + e);
            consume4(act, a0, a1, a2, a3, A0, A1, A2, A3);
            gather4(act, gwb, q0, laneoff, A0, A1, A2, A3);
            int4 q1 = *(const int4*)(g_coff + e + 4);
            consume4(act, a0, a1, a2, a3, B0, B1, B2, B3);
            gather4(act, gwb, q1, laneoff, B0, B1, B2, B3);
        }
        consume4(act, a0, a1, a2, a3, A0, A1, A2, A3);
        consume4(act, a0, a1, a2, a3, B0, B1, B2, B3);
    }
    if (e + 4 <= end) {
        ulonglong2 A0, A1, A2, A3;
        int4 qa = *(const int4*)(g_coff + e);
        gather4(act, gwb, qa, laneoff, A0, A1, A2, A3);
        consume4(act, a0, a1, a2, a3, A0, A1, A2, A3);
        e += 4;
    }
    for (; e < end; ++e) {
        if (act) {
            ulonglong2 v = *(const ulonglong2*)(gwb + g_coff[e] + laneoff);
            fadd2(a0, v.x); fadd2(a1, v.y);
        }
    }

    fadd2(a0, a2);
    fadd2(a1, a3);
    float2 lo = unpack2(a0);
    float2 hi = unpack2(a1);
    float den = __shfl_sync(0xffffffffu, lo.x, 25);     // lane 25 accumulated w
    float inv = (end > beg) ? (1.f / den) : 0.f;

    float4 r = make_float4(0.f, 0.f, 0.f, 0.f);
    if (lane < 25) {
        r.x = tanha(lo.x * inv);
        r.y = tanha(lo.y * inv);
        r.z = tanha(hi.x * inv);
        r.w = tanha(hi.y * inv);
        *(float4*)(out + (size_t)row * OUTD + outoff + lane * 4) = r;
    }
    if (!LAST)
        epilogue_store(r, lane, row, buf ^ 1);
}

// ---------------------------------------------------------------------------
extern "C" void kernel_launch(void* const* d_in, const int* in_sizes, int n_in,
                              void* d_out, int out_size) {
    const float* features = (const float*)d_in[0];
    // d_in[1] = rel_emb: unused by the reference computation.
    const int* adj        = (const int*)d_in[2];   // int32 pairs (JAX demotes int64)
    const float* none_rel = (const float*)d_in[3];
    float* out = (float*)d_out;

    prep_kernel<<<(E_EDGES + 255) / 256, 256>>>(adj, none_rel);
    tanh_score_kernel<<<(N_NODES * 32 + 255) / 256, 256>>>(features, out);
    const int RB = (N_NODES * 32 + 127) / 128;
    row_kernel<false><<<RB, 128>>>(0, out, D);
    row_kernel<true ><<<RB, 128>>>(1, out, 2 * D);
}

// round 14
// speedup vs baseline: 1.0964x; 1.0964x over previous
#include <cuda_runtime.h>
#include <math.h>

#define N_NODES 50000
#define D 100
#define DP 128      // padded row: 100 premult feats + w @slot100 + pad -> 512B, line-aligned
#define E_EDGES 800000
#define OUTD 300

// Scratch (allocation-free). g_gw[b][node*DP..] = [w*f[0..99], w, pad...].
// Rows are 512B = exactly 4 aligned 128B cache lines -> 4 L1 wavefronts/edge.
// w[c] = exp(score[c]); score in [-1,1] so exp never overflows and the
// reference's max-subtraction cancels exactly in the softmax ratio.
__device__ __align__(128) float g_gw[2][(size_t)N_NODES * DP];
__device__ __align__(16) float g_nr[128];
__device__ __align__(16) int g_coff[E_EDGES + 32];
__device__ int g_rowptr[N_NODES + 1];

typedef unsigned long long u64;

// ---------------------------------------------------------------------------
__device__ __forceinline__ void fadd2(u64& a, u64 b) {
    asm("add.rn.f32x2 %0, %0, %1;" : "+l"(a) : "l"(b));
}
__device__ __forceinline__ float2 unpack2(u64 v) {
    float2 r;
    asm("mov.b64 {%0, %1}, %2;" : "=f"(r.x), "=f"(r.y) : "l"(v));
    return r;
}
__device__ __forceinline__ float tanha(float x) {      // HW tanh approx
    float r;
    asm("tanh.approx.f32 %0, %1;" : "=f"(r) : "f"(x));
    return r;
}

// ---------------------------------------------------------------------------
// Prep: packed col offsets (col << 7) + CSR row pointers (rows sorted).
// Block 0 threads 0..127 additionally build the normalized none_relation.
__global__ void prep_kernel(const int* __restrict__ adj,
                            const float* __restrict__ none_rel) {
    if (blockIdx.x == 0 && threadIdx.x < 128) {
        __shared__ float ssum[128];
        int t = threadIdx.x;
        float v = (t < D) ? none_rel[t] : 0.f;
        ssum[t] = v * v;
        __syncthreads();
        for (int s = 64; s > 0; s >>= 1) {
            if (t < s) ssum[t] += ssum[t + s];
            __syncthreads();
        }
        float inv = 1.f / fmaxf(sqrtf(ssum[0]), 1e-12f);
        g_nr[t] = (t < D) ? v * inv : 0.f;
    }
    int i = blockIdx.x * blockDim.x + threadIdx.x;
    if (i < E_EDGES)
        g_coff[i] = adj[2 * i + 1] << 7;
    if (i <= N_NODES) {
        int lo = 0, hi = E_EDGES;
        while (lo < hi) {
            int mid = (lo + hi) >> 1;
            if (adj[2 * mid] < i) lo = mid + 1; else hi = mid;
        }
        g_rowptr[i] = lo;
    }
}

// ---------------------------------------------------------------------------
// Warp-collective epilogue: from this node's fp32 feature chunk r (lanes 0..24),
// compute w = exp(-dot(l2norm(r), nr)); store [w*r, w, ...] into g_gw[fbuf].
__device__ __forceinline__ void epilogue_store(float4 r, int lane, int node, int fbuf) {
    float dot = 0.f, ss = 0.f;
    if (lane < 25) {
        float4 nv = *(const float4*)(g_nr + lane * 4);
        dot = r.x * nv.x + r.y * nv.y + r.z * nv.z + r.w * nv.w;
        ss  = r.x * r.x + r.y * r.y + r.z * r.z + r.w * r.w;
    }
    #pragma unroll
    for (int o = 16; o; o >>= 1) {
        dot += __shfl_xor_sync(0xffffffffu, dot, o);
        ss  += __shfl_xor_sync(0xffffffffu, ss, o);
    }
    float w = __expf(-dot / fmaxf(sqrtf(ss), 1e-12f));
    if (lane < 26) {
        float4 s = (lane < 25)
            ? make_float4(w * r.x, w * r.y, w * r.z, w * r.w)
            : make_float4(w, 0.f, 0.f, 0.f);
        *(float4*)(g_gw[fbuf] + ((size_t)node << 7) + lane * 4) = s;
    }
}

// ---------------------------------------------------------------------------
// Layer 0: r = tanh(features); write out cols [0,D), build g_gw[0].
__global__ void tanh_score_kernel(const float* __restrict__ feat,
                                  float* __restrict__ out) {
    int node = (blockIdx.x * blockDim.x + threadIdx.x) >> 5;
    int lane = threadIdx.x & 31;
    if (node >= N_NODES) return;
    float4 r = make_float4(0.f, 0.f, 0.f, 0.f);
    if (lane < 25) {
        float4 v = *(const float4*)(feat + (size_t)node * D + lane * 4);
        r.x = tanha(v.x); r.y = tanha(v.y); r.z = tanha(v.z); r.w = tanha(v.w);
        *(float4*)(out + (size_t)node * OUTD + lane * 4) = r;
    }
    epilogue_store(r, lane, node, 0);
}

// ---------------------------------------------------------------------------
// Attention row kernel (R11 shape: light 2-stage pipeline, 128-thr blocks).
// Lanes 0..24 accumulate features; lane 25's first slot accumulates den.
template <bool LAST>
__global__ void __launch_bounds__(128) row_kernel(int buf, float* __restrict__ out,
                                                  int outoff) {
    int row = (blockIdx.x * blockDim.x + threadIdx.x) >> 5;
    int lane = threadIdx.x & 31;
    if (row >= N_NODES) return;
    int beg = g_rowptr[row];
    int end = g_rowptr[row + 1];
    const float* __restrict__ gwb = g_gw[buf];
    bool act = (lane < 26);
    int laneoff = lane * 4;

    u64 a0 = 0ull, a1 = 0ull, a2 = 0ull, a3 = 0ull;

    int e = beg;
    // Peel to int4-aligned coff reads.
    int pre = (4 - (beg & 3)) & 3;
    if (pre > end - beg) pre = end - beg;
    for (int k = 0; k < pre; ++k, ++e) {
        if (act) {
            ulonglong2 v = *(const ulonglong2*)(gwb + g_coff[e] + laneoff);
            fadd2(a0, v.x); fadd2(a1, v.y);
        }
    }

    if (e + 4 <= end) {
        ulonglong2 cv0, cv1, cv2, cv3;
        {
            int4 q = *(const int4*)(g_coff + e);
            if (act) {
                cv0 = *(const ulonglong2*)(gwb + q.x + laneoff);
                cv1 = *(const ulonglong2*)(gwb + q.y + laneoff);
                cv2 = *(const ulonglong2*)(gwb + q.z + laneoff);
                cv3 = *(const ulonglong2*)(gwb + q.w + laneoff);
            }
        }
        e += 4;
        for (; e + 4 <= end; e += 4) {
            int4 q = *(const int4*)(g_coff + e);
            ulonglong2 nv0, nv1, nv2, nv3;
            if (act) {
                nv0 = *(const ulonglong2*)(gwb + q.x + laneoff);
                nv1 = *(const ulonglong2*)(gwb + q.y + laneoff);
                nv2 = *(const ulonglong2*)(gwb + q.z + laneoff);
                nv3 = *(const ulonglong2*)(gwb + q.w + laneoff);
                fadd2(a0, cv0.x); fadd2(a1, cv0.y);
                fadd2(a2, cv1.x); fadd2(a3, cv1.y);
                fadd2(a0, cv2.x); fadd2(a1, cv2.y);
                fadd2(a2, cv3.x); fadd2(a3, cv3.y);
                cv0 = nv0; cv1 = nv1; cv2 = nv2; cv3 = nv3;
            }
        }
        if (act) {
            fadd2(a0, cv0.x); fadd2(a1, cv0.y);
            fadd2(a2, cv1.x); fadd2(a3, cv1.y);
            fadd2(a0, cv2.x); fadd2(a1, cv2.y);
            fadd2(a2, cv3.x); fadd2(a3, cv3.y);
        }
    }
    for (; e < end; ++e) {
        if (act) {
            ulonglong2 v = *(const ulonglong2*)(gwb + g_coff[e] + laneoff);
            fadd2(a0, v.x); fadd2(a1, v.y);
        }
    }

    fadd2(a0, a2);
    fadd2(a1, a3);
    float2 lo = unpack2(a0);
    float2 hi = unpack2(a1);
    float den = __shfl_sync(0xffffffffu, lo.x, 25);     // lane 25 accumulated w
    float inv = (end > beg) ? (1.f / den) : 0.f;

    float4 r = make_float4(0.f, 0.f, 0.f, 0.f);
    if (lane < 25) {
        r.x = tanha(lo.x * inv);
        r.y = tanha(lo.y * inv);
        r.z = tanha(hi.x * inv);
        r.w = tanha(hi.y * inv);
        *(float4*)(out + (size_t)row * OUTD + outoff + lane * 4) = r;
    }
    if (!LAST)
        epilogue_store(r, lane, row, buf ^ 1);
}

// ---------------------------------------------------------------------------
extern "C" void kernel_launch(void* const* d_in, const int* in_sizes, int n_in,
                              void* d_out, int out_size) {
    const float* features = (const float*)d_in[0];
    // d_in[1] = rel_emb: unused by the reference computation.
    const int* adj        = (const int*)d_in[2];   // int32 pairs (JAX demotes int64)
    const float* none_rel = (const float*)d_in[3];
    float* out = (float*)d_out;

    prep_kernel<<<(E_EDGES + 255) / 256, 256>>>(adj, none_rel);
    tanh_score_kernel<<<(N_NODES * 32 + 255) / 256, 256>>>(features, out);
    const int RB = (N_NODES * 32 + 127) / 128;
    row_kernel<false><<<RB, 128>>>(0, out, D);
    row_kernel<true ><<<RB, 128>>>(1, out, 2 * D);
}